// round 8
// baseline (speedup 1.0000x reference)
#include <cuda_runtime.h>
#include <math.h>

#define B_ 32
#define L_ 512
#define D_ 768
#define C_ 97
#define GM (B_*C_)
#define BL (B_*L_)

// ---------------- scalar slots ----------------
// 0:ps1[32] 32:ps2 64:sagx0 96:P1g0 128:P2g0 160:sagx1a 192:sagx1b
// 224:P1g1 256:P2g1 288:sag1p
#define NSC 544

// ---------------- scratch ----------------
__device__ float g_bpart[24*B_*D_];  // grp0..7: a2@x0; grp8..15: pos1.x0; grp16..23: pos2.x0
__device__ float g_kv[4*D_];
__device__ float g_gv[4*D_];
__device__ float g_R[4*BL];
__device__ float g_g0[BL];
__device__ float g_a2[BL];
__device__ float g_sc[NSC];
__device__ float g_p0[C_*D_];
__device__ float g_pd[512];
__device__ float g_u0[D_];
__device__ float g_ctxA0[D_];
__device__ float g_cA1p[B_*D_];      // 2*(a1@P0V)+vb2 (direct store)
__device__ float g_CV[B_*D_];        // ctx2_0@vw2 (atomic)
__device__ float g_ctx2[B_*D_];      // ctx2_0 only (atomic)
__device__ float g_t1[B_*D_];
__device__ float g_pcw[161*D_];      // rows0-96 p0W, 97-128 ctx2_0W, 129-160 u21@VF1
__device__ float g_p0v[C_*D_];       // p0@vw2 (atomic)
__device__ float g_vf1[768*D_];      // vw3@fc1w (direct)
__device__ float g_vbf[D_];          // vb3@fc1w (direct)
__device__ float g_w3g[D_];          // row dots vw3 . gw3
__device__ float g_misc[4];          // [0] = vb3.gw3 + gb3

__device__ __forceinline__ float warpsum(float v){
#pragma unroll
    for (int o = 16; o > 0; o >>= 1) v += __shfl_xor_sync(0xffffffffu, v, o);
    return v;
}
__device__ __forceinline__ float warpmax(float v){
#pragma unroll
    for (int o = 16; o > 0; o >>= 1) v = fmaxf(v, __shfl_xor_sync(0xffffffffu, v, o));
    return v;
}
__device__ __forceinline__ float sigm(float z){ return 1.f/(1.f + expf(-z)); }
__device__ __forceinline__ unsigned f2tf(float f){
    unsigned u; asm("cvt.rna.tf32.f32 %0, %1;" : "=r"(u) : "f"(f)); return u;
}
__device__ __forceinline__ void mma_tf32(float c[4], unsigned a0, unsigned a1,
                                         unsigned a2, unsigned a3,
                                         unsigned b0, unsigned b1){
    asm volatile("mma.sync.aligned.m16n8k8.row.col.f32.tf32.tf32.f32 "
        "{%0,%1,%2,%3}, {%4,%5,%6,%7}, {%8,%9}, {%0,%1,%2,%3};\n"
        : "+f"(c[0]), "+f"(c[1]), "+f"(c[2]), "+f"(c[3])
        : "r"(a0), "r"(a1), "r"(a2), "r"(a3), "r"(b0), "r"(b1));
}
__device__ __forceinline__ float blockdot768(const float* __restrict__ a,
                                             const float* __restrict__ v,
                                             float* sh, int nthr){
    int tid = threadIdx.x, lane = tid & 31, w = tid >> 5;
    float p = 0.f;
    for (int e = tid; e < D_; e += nthr) p += a[e]*v[e];
    p = warpsum(p);
    __syncthreads();
    if (!lane) sh[w] = p;
    __syncthreads();
    float r = 0.f;
    int nw = nthr >> 5;
    for (int i = 0; i < nw; i++) r += sh[i];
    return r;
}
__device__ __forceinline__ float sum8(int g0, int b, int e){
    float s = 0.f;
#pragma unroll
    for (int g = 0; g < 8; g++) s += g_bpart[((size_t)(g0+g)*B_+b)*D_ + e];
    return s;
}

// ---------------- zero p0 ----------------
__global__ void k_zp0(){
    int i = blockIdx.x*256 + threadIdx.x;
    if (i < C_*D_) g_p0[i] = 0.f;
}

// ---------------- zeros + kv/gv prep ----------------
__global__ void __launch_bounds__(256) k_prepzero(const float* __restrict__ kw,
                                                  const float* __restrict__ sw,
                                                  const float* __restrict__ gw){
    int gtid = blockIdx.x*blockDim.x + threadIdx.x;
    if (gtid < NSC) g_sc[gtid] = 0.f;
    if (gtid < D_) g_ctxA0[gtid] = 0.f;
    if (gtid < B_*D_){ g_CV[gtid] = 0.f; g_t1[gtid] = 0.f; g_ctx2[gtid] = 0.f; }
    if (gtid < 161*D_) g_pcw[gtid] = 0.f;
    if (gtid < C_*D_) g_p0v[gtid] = 0.f;
    if (gtid < 4*D_){
        int ra = gtid/D_, dd = gtid%D_;
        const float* g = gw + (size_t)ra*2*D_;
        g_gv[gtid] = g[dd] + g[D_+dd];
    }
    int wid = gtid >> 5, lane = gtid & 31;
    if (wid < 4*D_){
        int ra = wid/D_, d = wid%D_;
        const float* krow = kw + ((size_t)ra*D_ + d)*D_;
        const float* s2   = sw + (size_t)ra*2*D_ + D_;
        float acc = 0.f;
        for (int e = lane; e < D_; e += 32) acc += krow[e]*s2[e];
        acc = warpsum(acc);
        if (!lane) g_kv[wid] = acc;
    }
}

// ---------------- weight-only prep: W3G row dots + svbg ----------------
__global__ void __launch_bounds__(256) k_wprep(const float* __restrict__ vw3,
                                               const float* __restrict__ gw3,
                                               const float* __restrict__ vb3,
                                               const float* __restrict__ gb3){
    int wid = threadIdx.x >> 5, lane = threadIdx.x & 31;
    if (blockIdx.x < 96){
        int row = blockIdx.x*8 + wid;
        const float* r = vw3 + (size_t)row*D_;
        float acc = 0.f;
        for (int e = lane; e < D_; e += 32) acc += r[e]*gw3[e];
        acc = warpsum(acc);
        if (!lane) g_w3g[row] = acc;
    } else if (wid == 0){
        float acc = 0.f;
        for (int e = lane; e < D_; e += 32) acc += vb3[e]*gw3[e];
        acc = warpsum(acc);
        if (!lane) g_misc[0] = acc + gb3[0];
    }
}

// ---------------- one pass over x0 (8 chunks of 64 rows) ----------------
__global__ void __launch_bounds__(256) k_xprep(const float* __restrict__ x0,
                                               const float* __restrict__ pos1,
                                               const float* __restrict__ pos2){
    int blk = blockIdx.x; int b = blk >> 3, ch = blk & 7;
    int tid = threadIdx.x;
    int wid = tid >> 5, lane = tid & 31;
    int base = b*L_ + ch*64;
    for (int r = wid; r < 64; r += 8){
        const float* xr = x0 + (size_t)(base+r)*D_;
        float a0=0.f, a1=0.f, a2=0.f, a3=0.f;
#pragma unroll
        for (int j = 0; j < 24; j++){
            int e = lane + j*32; float xv = xr[e];
            a0 += xv*g_gv[e];
            a1 += xv*g_kv[D_+e];
            a2 += xv*g_gv[2*D_+e];
            a3 += xv*g_kv[3*D_+e];
        }
        a0=warpsum(a0); a1=warpsum(a1); a2=warpsum(a2); a3=warpsum(a3);
        if (!lane){
            int row = base + r;
            g_R[row] = a0; g_R[BL+row] = a1; g_R[2*BL+row] = a2; g_R[3*BL+row] = a3;
        }
    }
    __shared__ float s1[64], s2[64];
    if (tid < 64){ s1[tid] = pos1[base+tid]; s2[tid] = pos2[base+tid]; }
    __syncthreads();
#pragma unroll
    for (int c0 = 0; c0 < 3; c0++){
        int col = tid + c0*256;
        const float* xb = x0 + (size_t)base*D_ + col;
        float e1 = 0.f, e2 = 0.f;
#pragma unroll 8
        for (int l = 0; l < 64; l++){
            float xv = xb[(size_t)l*D_];
            e1 += s1[l]*xv; e2 += s2[l]*xv;
        }
        g_bpart[((size_t)(8+ch)*B_ + b)*D_ + col] = e1;
        g_bpart[((size_t)(16+ch)*B_ + b)*D_ + col] = e2;
    }
    if (tid == 0){
        float t1 = 0.f, t2 = 0.f;
        for (int l = 0; l < 64; l++){ t1 += s1[l]; t2 += s2[l]; }
        atomicAdd(&g_sc[b], t1); atomicAdd(&g_sc[32+b], t2);
    }
}

// ---------------- fused: pdots + layer0 softmax + u0 ----------------
__global__ void __launch_bounds__(1024) k_l0fused(){
    __shared__ float a[C_];
    int tid = threadIdx.x;
    int wid = tid >> 5, lane = tid & 31;
    for (int c = wid; c < C_; c += 32){
        const float* pr = g_p0 + (size_t)c*D_;
        float a0=0.f,a1=0.f,a2=0.f,a3=0.f;
#pragma unroll
        for (int j=0;j<24;j++){
            int e = lane + j*32; float pv = pr[e];
            a0 += pv*g_kv[e];
            a1 += pv*g_kv[2*D_+e];
            a2 += pv*g_gv[D_+e];
            a3 += pv*g_gv[3*D_+e];
        }
        a0=warpsum(a0);a1=warpsum(a1);a2=warpsum(a2);a3=warpsum(a3);
        if (!lane){ g_pd[c]=a0; g_pd[128+c]=a1; g_pd[256+c]=a2; g_pd[384+c]=a3;
                    a[c] = a0; }
    }
    __syncthreads();
    if (tid == 0){
        float m = -1e30f;
        for (int c=0;c<C_;c++) m = fmaxf(m, a[c]);
        float s = 0.f;
        for (int c=0;c<C_;c++){ a[c] = expf(a[c]-m); s += a[c]; }
        float inv = 1.f/s;
        for (int c=0;c<C_;c++) a[c] *= inv;
    }
    __syncthreads();
    if (tid < D_){
        float acc = 0.f;
        for (int c=0;c<C_;c++) acc += a[c]*g_p0[(size_t)c*D_+tid];
        g_u0[tid] = acc;
    }
}

// ---------------- GEMV (atomic, split-8): ctxA0 = u0@W + bias ----------------
__global__ void __launch_bounds__(128) k_gemv(const float* __restrict__ W,
                                              const float* __restrict__ bias){
    int n = blockIdx.x*128 + threadIdx.x;
    int kc = blockIdx.y;
    float acc = (kc==0) ? bias[n] : 0.f;
    const float* Wp = W + (size_t)kc*96*D_ + n;
    const float* u = g_u0 + kc*96;
#pragma unroll 4
    for (int k=0;k<96;k++) acc += u[k]*Wp[(size_t)k*D_];
    atomicAdd(&g_ctxA0[n], acc);
}

// ---------------- full GEMV (direct store): out = u@W ----------------
__global__ void __launch_bounds__(128) k_gemv_full(const float* __restrict__ u,
                                                   const float* __restrict__ W,
                                                   float* __restrict__ out){
    int n = blockIdx.x*128 + threadIdx.x;
    const float* Wp = W + n;
    float acc = 0.f;
#pragma unroll 4
    for (int k=0;k<768;k++) acc += u[k]*Wp[(size_t)k*D_];
    out[n] = acc;
}

// ---------------- gates + masked softmax + scalar reductions ----------------
__global__ void __launch_bounds__(512) k_gates(int li, const int* __restrict__ mask,
                        const float* __restrict__ pos1, const float* __restrict__ pos2,
                        const float* __restrict__ gwp, const float* __restrict__ gbp){
    int b = blockIdx.x, tid = threadIdx.x;
    __shared__ float sh[16];
    __shared__ float sc[4];
    if (li == 0){
        float d0 = blockdot768(g_ctxA0, gwp, sh, 512);
        float d1 = blockdot768(g_ctxA0, g_kv + D_, sh, 512);
        if (tid == 0){ sc[0] = d0 + gbp[0]; sc[1] = d1; }
    } else {
        const float* cp = g_cA1p + (size_t)b*D_;
        const float* cv = g_CV + (size_t)b*D_;
        float sag = g_sc[288+b];
        float d0a = blockdot768(cp, gwp, sh, 512);
        float d0b = blockdot768(cv, gwp, sh, 512);
        float d1 = blockdot768(g_ctxA0, g_gv + 2*D_, sh, 512);
        float d2 = blockdot768(g_ctxA0, g_kv + 3*D_, sh, 512);
        float d3a = blockdot768(cp, g_kv + 3*D_, sh, 512);
        float d3b = blockdot768(cv, g_kv + 3*D_, sh, 512);
        if (tid == 0){
            sc[0] = d0a + sag*d0b + gbp[0];
            sc[1] = d1; sc[2] = d2;
            sc[3] = d3a + sag*d3b;
        }
    }
    __syncthreads();
    int row = b*L_ + tid;
    float g, sk, g0v = 0.f;
    if (li == 0){
        g = sigm(g_R[row] + sc[0]);
        sk = 2.f*g_R[BL+row] + g*sc[1];
        g_g0[row] = g;
    } else {
        g0v = g_g0[row];
        g = sigm(2.f*g_R[2*BL+row] + g0v*sc[1] + sc[0]);
        sk = 4.f*g_R[3*BL+row] + 2.f*g0v*sc[2] + g*sc[3];
    }
    if (!mask[row]) sk = -1e30f;
    __shared__ float sm[16];
    __shared__ float bc;
    float m = warpmax(sk);
    if ((tid & 31) == 0) sm[tid>>5] = m;
    __syncthreads();
    if (tid == 0){
        float mm = sm[0];
        for (int i = 1; i < 16; i++) mm = fmaxf(mm, sm[i]);
        bc = mm;
    }
    __syncthreads();
    float e = expf(sk - bc);
    float ssum = warpsum(e);
    __syncthreads();
    if ((tid & 31) == 0) sm[tid>>5] = ssum;
    __syncthreads();
    if (tid == 0){
        float ss = 0.f;
        for (int i = 0; i < 16; i++) ss += sm[i];
        bc = ss;
    }
    __syncthreads();
    float a = e / bc;
    g_a2[row] = a;
    __shared__ float red[16][4];
    float r0, r1, r2, r3;
    if (li == 0){ r0 = a*g; r1 = pos1[row]*g; r2 = pos2[row]*g; r3 = 0.f; }
    else        { r0 = a*g0v; r1 = a*g; r2 = pos1[row]*g; r3 = pos2[row]*g; }
    r0=warpsum(r0); r1=warpsum(r1); r2=warpsum(r2); r3=warpsum(r3);
    if ((tid & 31) == 0){
        int w = tid>>5;
        red[w][0]=r0; red[w][1]=r1; red[w][2]=r2; red[w][3]=r3;
    }
    __syncthreads();
    if (tid == 0){
        float t0=0,t1=0,t2=0,t3=0;
        for (int i = 0; i < 16; i++){ t0+=red[i][0]; t1+=red[i][1]; t2+=red[i][2]; t3+=red[i][3]; }
        if (li == 0){ g_sc[64+b]=t0; g_sc[96+b]=t1; g_sc[128+b]=t2; }
        else        { g_sc[160+b]=t0; g_sc[192+b]=t1; g_sc[224+b]=t2; g_sc[256+b]=t3; }
    }
}

// ---------------- passB: a2 @ x0 partials (8 chunks) ----------------
__global__ void __launch_bounds__(256) k_passB(const float* __restrict__ x0){
    int blk = blockIdx.x; int b = blk >> 3, ch = blk & 7;
    int tid = threadIdx.x;
    __shared__ float sa[64];
    if (tid < 64) sa[tid] = g_a2[b*L_ + ch*64 + tid];
    __syncthreads();
#pragma unroll
    for (int c0 = 0; c0 < 3; c0++){
        int col = tid + c0*256;
        const float* xb = x0 + ((size_t)b*L_ + ch*64)*D_ + col;
        float au = 0.f;
#pragma unroll 8
        for (int l = 0; l < 64; l++) au += sa[l]*xb[(size_t)l*D_];
        g_bpart[((size_t)ch*B_ + b)*D_ + col] = au;
    }
}

// ---------------- layer1 RA1: softmax over C + cA1p = 2*(a1@P0V)+vb2 ----------------
__global__ void __launch_bounds__(256) k_ra1_l1(const float* __restrict__ gwp,
                                                const float* __restrict__ gbp,
                                                const float* __restrict__ vb2){
    int b = blockIdx.x, tid = threadIdx.x;
    __shared__ float sh[8];
    __shared__ float sc2[2];
    __shared__ float a1[C_], g0p[C_];
    const float* c20 = g_ctx2 + (size_t)b*D_;
    float d0 = blockdot768(c20, gwp, sh, 256);
    float d1 = blockdot768(c20, g_kv + 2*D_, sh, 256);
    if (tid == 0){ sc2[0] = d0 + gbp[0]; sc2[1] = d1; }
    __syncthreads();
    if (tid < C_){
        float gp = sigm(g_pd[256+tid] + sc2[0]);
        g0p[tid] = gp;
        a1[tid] = 2.f*g_pd[128+tid] + gp*sc2[1];
    }
    __syncthreads();
    if (tid == 0){
        float m = -1e30f;
        for (int c=0;c<C_;c++) m = fmaxf(m, a1[c]);
        float s = 0.f;
        for (int c=0;c<C_;c++){ a1[c] = expf(a1[c]-m); s += a1[c]; }
        float inv = 1.f/s, sg = 0.f;
        for (int c=0;c<C_;c++){ a1[c] *= inv; sg += a1[c]*g0p[c]; }
        g_sc[288+b] = sg;
    }
    __syncthreads();
    for (int n = tid; n < D_; n += 256){
        float s = 0.f;
        for (int c=0;c<C_;c++) s += a1[c]*g_p0v[(size_t)c*D_+n];
        g_cA1p[b*D_+n] = 2.f*s + vb2[n];
    }
}

// ---------------- A-assembly ----------------
__device__ __forceinline__ float4 f4sum8(int g0, int m, int kg){
    float4 s = make_float4(0.f,0.f,0.f,0.f);
#pragma unroll
    for (int g = 0; g < 8; g++){
        float4 v = *(const float4*)(g_bpart + ((size_t)(g0+g)*B_+m)*D_ + kg);
        s.x += v.x; s.y += v.y; s.z += v.z; s.w += v.w;
    }
    return s;
}
__device__ __forceinline__ float4 loadA4(const float* __restrict__ A, int amode,
                                         int m, int M, int kg, int K){
    if (m >= M) return make_float4(0.f,0.f,0.f,0.f);
    if (amode == 0) return *(const float4*)(A + (size_t)m*K + kg);
    if (amode == 1){
        float4 s = f4sum8(0, m, kg);
        float4 c = *(const float4*)(g_ctxA0 + kg);
        float sg = g_sc[64+m];
        return make_float4(2.f*s.x+sg*c.x, 2.f*s.y+sg*c.y, 2.f*s.z+sg*c.z, 2.f*s.w+sg*c.w);
    }
    if (amode == 2){
        float4 s = f4sum8(0, m, kg);
        float4 c0 = *(const float4*)(g_ctxA0 + kg);
        float4 p = *(const float4*)(g_cA1p + (size_t)m*D_ + kg);
        float4 cv = *(const float4*)(g_CV + (size_t)m*D_ + kg);
        float sag = g_sc[288+m];
        float sa = 2.f*g_sc[160+m], sb = g_sc[192+m];
        return make_float4(4.f*s.x+sa*c0.x+sb*(p.x+sag*cv.x),
                           4.f*s.y+sa*c0.y+sb*(p.y+sag*cv.y),
                           4.f*s.z+sa*c0.z+sb*(p.z+sag*cv.z),
                           4.f*s.w+sa*c0.w+sb*(p.w+sag*cv.w));
    }
    // amode 3: e12
    int g0 = (kg < D_) ? 8 : 16;
    int k2 = (kg < D_) ? kg : kg - D_;
    float4 s = f4sum8(g0, m, k2);
    float4 c0 = *(const float4*)(g_ctxA0 + k2);
    float4 p = *(const float4*)(g_cA1p + (size_t)m*D_ + k2);
    float4 cv = *(const float4*)(g_CV + (size_t)m*D_ + k2);
    float sag = g_sc[288+m];
    float pg0 = 2.f*((kg < D_) ? g_sc[96+m] : g_sc[128+m]);
    float pg1 = (kg < D_) ? g_sc[224+m] : g_sc[256+m];
    float inv = 1.f/((kg < D_) ? g_sc[m] : g_sc[32+m]);
    return make_float4((4.f*s.x+pg0*c0.x+pg1*(p.x+sag*cv.x))*inv,
                       (4.f*s.y+pg0*c0.y+pg1*(p.y+sag*cv.y))*inv,
                       (4.f*s.z+pg0*c0.z+pg1*(p.z+sag*cv.z))*inv,
                       (4.f*s.w+pg0*c0.w+pg1*(p.w+sag*cv.w))*inv);
}

// ---------------- generic 128-row TF32 split-K GEMM ----------------
__global__ void __launch_bounds__(256) k_tcgemm(const float* __restrict__ A,
        const float* __restrict__ W, float* __restrict__ out,
        const float* __restrict__ bias, int M, int K, int KCH, int amode){
    __shared__ unsigned As[2][128][20];
    __shared__ unsigned Bs[2][16][132];
    int tid = threadIdx.x;
    int lane = tid & 31, g = lane >> 2, tg = lane & 3;
    int wid = tid >> 5, wm = wid >> 2, wn = wid & 3;
    int n0 = blockIdx.x * 128;
    int kb = blockIdx.y;
    int m0 = blockIdx.z * 128;
    int kbase = kb * KCH;
    int NS = KCH / 16;
    bool direct = (gridDim.y == 1);

    float cacc[4][4][4];
#pragma unroll
    for (int i = 0; i < 4; i++)
#pragma unroll
        for (int j = 0; j < 4; j++)
#pragma unroll
            for (int q = 0; q < 4; q++) cacc[i][j][q] = 0.f;

    int a_r = tid >> 2, a_c = (tid & 3) * 4;
    int b_r = tid >> 5, b_c = (tid & 31) * 4;

    float4 pa[2], pb[2];
#pragma unroll
    for (int r = 0; r < 2; r++){
        pa[r] = loadA4(A, amode, m0 + a_r + r*64, M, kbase + a_c, K);
        pb[r] = *(const float4*)(W + (size_t)(kbase + b_r + r*8)*D_ + n0 + b_c);
    }
#pragma unroll
    for (int r = 0; r < 2; r++){
        uint4 ua = { f2tf(pa[r].x), f2tf(pa[r].y), f2tf(pa[r].z), f2tf(pa[r].w) };
        *(uint4*)&As[0][a_r + r*64][a_c] = ua;
        uint4 ub = { f2tf(pb[r].x), f2tf(pb[r].y), f2tf(pb[r].z), f2tf(pb[r].w) };
        *(uint4*)&Bs[0][b_r + r*8][b_c] = ub;
    }
    __syncthreads();

    for (int s = 0; s < NS; s++){
        int cur = s & 1;
        if (s < NS-1){
            int kg = kbase + (s+1)*16;
#pragma unroll
            for (int r = 0; r < 2; r++){
                pa[r] = loadA4(A, amode, m0 + a_r + r*64, M, kg + a_c, K);
                pb[r] = *(const float4*)(W + (size_t)(kg + b_r + r*8)*D_ + n0 + b_c);
            }
        }
#pragma unroll
        for (int ks = 0; ks < 2; ks++){
            int k8 = ks*8;
            unsigned af[4][4], bf[4][2];
#pragma unroll
            for (int i = 0; i < 4; i++){
                int r = wm*64 + i*16 + g;
                af[i][0] = As[cur][r][k8+tg];
                af[i][1] = As[cur][r+8][k8+tg];
                af[i][2] = As[cur][r][k8+tg+4];
                af[i][3] = As[cur][r+8][k8+tg+4];
            }
#pragma unroll
            for (int j = 0; j < 4; j++){
                int c0 = wn*32 + j*8 + g;
                bf[j][0] = Bs[cur][k8+tg][c0];
                bf[j][1] = Bs[cur][k8+tg+4][c0];
            }
#pragma unroll
            for (int i = 0; i < 4; i++)
#pragma unroll
                for (int j = 0; j < 4; j++)
                    mma_tf32(cacc[i][j], af[i][0], af[i][1], af[i][2], af[i][3],
                             bf[j][0], bf[j][1]);
        }
        if (s < NS-1){
            int nxt = cur ^ 1;
#pragma unroll
            for (int r = 0; r < 2; r++){
                uint4 ua = { f2tf(pa[r].x), f2tf(pa[r].y), f2tf(pa[r].z), f2tf(pa[r].w) };
                *(uint4*)&As[nxt][a_r + r*64][a_c] = ua;
                uint4 ub = { f2tf(pb[r].x), f2tf(pb[r].y), f2tf(pb[r].z), f2tf(pb[r].w) };
                *(uint4*)&Bs[nxt][b_r + r*8][b_c] = ub;
            }
        }
        __syncthreads();
    }

#pragma unroll
    for (int i = 0; i < 4; i++){
#pragma unroll
        for (int half = 0; half < 2; half++){
            int m = m0 + wm*64 + i*16 + g + half*8;
            if (m < M){
#pragma unroll
                for (int j = 0; j < 4; j++){
                    int n = n0 + wn*32 + j*8 + 2*tg;
                    float v0 = cacc[i][j][half*2+0];
                    float v1 = cacc[i][j][half*2+1];
                    if (kb == 0 && bias){ v0 += bias[n]; v1 += bias[n+1]; }
                    if (direct){
                        out[(size_t)m*D_ + n] = v0;
                        out[(size_t)m*D_ + n + 1] = v1;
                    } else {
                        atomicAdd(out + (size_t)m*D_ + n,     v0);
                        atomicAdd(out + (size_t)m*D_ + n + 1, v1);
                    }
                }
            }
        }
    }
}

// ---------------- dedicated M=32 TF32 split-K GEMM ----------------
__global__ void __launch_bounds__(256) k_tcgemm32(const float* __restrict__ A,
        const float* __restrict__ W, float* __restrict__ out,
        const float* __restrict__ bias, int K, int KCH, int amode){
    __shared__ unsigned As[2][32][20];
    __shared__ unsigned Bs[2][16][132];
    const int M = 32;
    int tid = threadIdx.x;
    int lane = tid & 31, g = lane >> 2, tg = lane & 3;
    int wid = tid >> 5, wm = wid >> 2, wn = wid & 3;
    int n0 = blockIdx.x * 128;
    int kb = blockIdx.y;
    int kbase = kb * KCH;
    int NS = KCH / 16;
    bool direct = (gridDim.y == 1);

    float cacc[4][4];
#pragma unroll
    for (int j = 0; j < 4; j++)
#pragma unroll
        for (int q = 0; q < 4; q++) cacc[j][q] = 0.f;

    int a_r = tid >> 2, a_c = (tid & 3) * 4;
    int b_r = tid >> 5, b_c = (tid & 31) * 4;

    float4 pa = make_float4(0.f,0.f,0.f,0.f), pb[2];
    if (tid < 128) pa = loadA4(A, amode, a_r, M, kbase + a_c, K);
#pragma unroll
    for (int r = 0; r < 2; r++)
        pb[r] = *(const float4*)(W + (size_t)(kbase + b_r + r*8)*D_ + n0 + b_c);
    if (tid < 128){
        uint4 ua = { f2tf(pa.x), f2tf(pa.y), f2tf(pa.z), f2tf(pa.w) };
        *(uint4*)&As[0][a_r][a_c] = ua;
    }
#pragma unroll
    for (int r = 0; r < 2; r++){
        uint4 ub = { f2tf(pb[r].x), f2tf(pb[r].y), f2tf(pb[r].z), f2tf(pb[r].w) };
        *(uint4*)&Bs[0][b_r + r*8][b_c] = ub;
    }
    __syncthreads();

    for (int s = 0; s < NS; s++){
        int cur = s & 1;
        if (s < NS-1){
            int kg = kbase + (s+1)*16;
            if (tid < 128) pa = loadA4(A, amode, a_r, M, kg + a_c, K);
#pragma unroll
            for (int r = 0; r < 2; r++)
                pb[r] = *(const float4*)(W + (size_t)(kg + b_r + r*8)*D_ + n0 + b_c);
        }
#pragma unroll
        for (int ks = 0; ks < 2; ks++){
            int k8 = ks*8;
            unsigned af[4], bf[4][2];
            int r = wm*16 + g;
            af[0] = As[cur][r][k8+tg];
            af[1] = As[cur][r+8][k8+tg];
            af[2] = As[cur][r][k8+tg+4];
            af[3] = As[cur][r+8][k8+tg+4];
#pragma unroll
            for (int j = 0; j < 4; j++){
                int c0 = wn*32 + j*8 + g;
                bf[j][0] = Bs[cur][k8+tg][c0];
                bf[j][1] = Bs[cur][k8+tg+4][c0];
            }
#pragma unroll
            for (int j = 0; j < 4; j++)
                mma_tf32(cacc[j], af[0], af[1], af[2], af[3], bf[j][0], bf[j][1]);
        }
        if (s < NS-1){
            int nxt = cur ^ 1;
            if (tid < 128){
                uint4 ua = { f2tf(pa.x), f2tf(pa.y), f2tf(pa.z), f2tf(pa.w) };
                *(uint4*)&As[nxt][a_r][a_c] = ua;
            }
#pragma unroll
            for (int r = 0; r < 2; r++){
                uint4 ub = { f2tf(pb[r].x), f2tf(pb[r].y), f2tf(pb[r].z), f2tf(pb[r].w) };
                *(uint4*)&Bs[nxt][b_r + r*8][b_c] = ub;
            }
        }
        __syncthreads();
    }

#pragma unroll
    for (int half = 0; half < 2; half++){
        int m = wm*16 + g + half*8;
#pragma unroll
        for (int j = 0; j < 4; j++){
            int n = n0 + wn*32 + j*8 + 2*tg;
            float v0 = cacc[j][half*2+0];
            float v1 = cacc[j][half*2+1];
            if (kb == 0 && bias){ v0 += bias[n]; v1 += bias[n+1]; }
            if (direct){
                out[(size_t)m*D_ + n] = v0;
                out[(size_t)m*D_ + n + 1] = v1;
            } else {
                atomicAdd(out + (size_t)m*D_ + n,     v0);
                atomicAdd(out + (size_t)m*D_ + n + 1, v1);
            }
        }
    }
}

// ---------------- final: tanh recombination + logits + argmax ----------------
__global__ void __launch_bounds__(256) k_tanh(const float* __restrict__ gw,
        const float* __restrict__ gb, const float* __restrict__ fc2w,
        const float* __restrict__ fc2b, float* __restrict__ out,
        int wlog, int predoff){
    int b = blockIdx.x, tid = threadIdx.x, lane = tid & 31, wid = tid >> 5;
    __shared__ float sh[8];
    __shared__ float cw0[D_], cw1[D_], t1s[D_], w2[D_];
    __shared__ float sc3[3];
    __shared__ float lg[C_];
    const float* c20 = g_ctx2 + (size_t)b*D_;
    for (int e = tid; e < D_; e += 256){
        cw0[e] = g_pcw[(size_t)(97+b)*D_+e];
        cw1[e] = g_pcw[(size_t)(129+b)*D_+e];
        t1s[e] = g_t1[b*D_+e];
        w2[e]  = fc2w[e];
    }
    float d0 = blockdot768(c20, gw + 1*2*D_, sh, 256);
    float d1 = blockdot768(c20, g_gv + 3*D_, sh, 256);
    // d2 = (assembled u2_1) . W3G + (vb3.gw3 + gb3)
    float sa2 = g_sc[160+b], sb2 = g_sc[192+b], sag = g_sc[288+b];
    float pd2 = 0.f;
    for (int e = tid; e < D_; e += 256){
        float s8 = sum8(0, b, e);
        float c1 = g_cA1p[b*D_+e] + sag*g_CV[b*D_+e];
        float u = 4.f*s8 + 2.f*sa2*g_ctxA0[e] + sb2*c1;
        pd2 += u*g_w3g[e];
    }
    pd2 = warpsum(pd2);
    __syncthreads();
    if (!lane) sh[wid] = pd2;
    __syncthreads();
    float d2 = 0.f;
    for (int i = 0; i < 8; i++) d2 += sh[i];
    if (tid == 0){ sc3[0] = d0 + gb[1]; sc3[1] = d1; sc3[2] = d2 + g_misc[0]; }
    __syncthreads();
    for (int c = wid; c < C_; c += 8){
        float gp0 = sigm(g_pd[256+c] + sc3[0]);
        float gp1 = sigm(2.f*g_pd[384+c] + gp0*sc3[1] + sc3[2]);
        const float* pw = g_pcw + (size_t)c*D_;
        float acc = 0.f;
#pragma unroll
        for (int j = 0; j < 24; j++){
            int n = lane + j*32;
            float z = 4.f*pw[n] + 2.f*gp0*cw0[n] + gp1*cw1[n] + t1s[n];
            acc += tanhf(z)*w2[n];
        }
        acc = warpsum(acc);
        if (!lane){
            float l = sigm(acc + fc2b[0]);
            lg[c] = l;
            if (wlog) out[b*C_+c] = l;
        }
    }
    __syncthreads();
    if (tid == 0 && predoff >= 0){
        float best = lg[0]; int bi = 0;
        for (int c = 1; c < C_; c++)
            if (lg[c] > best){ best = lg[c]; bi = c; }
        out[predoff + b] = (float)bi;
    }
}

// ---------------- streams, created+warmed at load time ----------------
namespace {
struct GStreams {
    cudaStream_t s1 = 0, s2 = 0;
    cudaEvent_t ev0, evA, evP, evPV, evB, evC0, evCV, evVF, evQ, evW, evC, evT;
    bool ok = false;
    GStreams(){
        bool o = true;
        o = o && cudaStreamCreateWithFlags(&s1, cudaStreamNonBlocking) == cudaSuccess;
        o = o && cudaStreamCreateWithFlags(&s2, cudaStreamNonBlocking) == cudaSuccess;
        cudaEvent_t* evs[12] = {&ev0,&evA,&evP,&evPV,&evB,&evC0,&evCV,&evVF,&evQ,&evW,&evC,&evT};
        for (int i = 0; i < 12 && o; i++)
            o = o && cudaEventCreateWithFlags(evs[i], cudaEventDisableTiming) == cudaSuccess;
        if (o){
            k_zp0<<<291,256,0,s1>>>();
            k_zp0<<<291,256,0,s2>>>();
            o = o && cudaStreamSynchronize(s1) == cudaSuccess;
            o = o && cudaStreamSynchronize(s2) == cudaSuccess;
        }
        ok = o;
    }
};
GStreams gs;
}

// ---------------- host orchestration ----------------
extern "C" void kernel_launch(void* const* d_in, const int* in_sizes, int n_in,
                              void* d_out, int out_size){
    (void)in_sizes; (void)n_in;
    const float* x_in  = (const float*)d_in[0];
    const float* pos1  = (const float*)d_in[1];
    const float* pos2  = (const float*)d_in[2];
    const int*   mask  = (const int*)  d_in[3];
    const float* emb   = (const float*)d_in[4];
    const float* rel_w = (const float*)d_in[5];
    const float* rel_b = (const float*)d_in[6];
    const float* kw    = (const float*)d_in[9];
    const float* vw    = (const float*)d_in[11];
    const float* vb    = (const float*)d_in[12];
    const float* sw    = (const float*)d_in[13];
    const float* gw    = (const float*)d_in[15];
    const float* gb    = (const float*)d_in[16];
    const float* fc1w  = (const float*)d_in[17];
    const float* fc1b  = (const float*)d_in[18];
    const float* fc2w  = (const float*)d_in[19];
    const float* fc2b  = (const float*)d_in[20];
    float* out = (float*)d_out;

    float *p_p0, *p_ctx2, *p_t1, *p_pcw, *p_p0v, *p_vf1, *p_vbf, *p_CV;
    cudaGetSymbolAddress((void**)&p_p0,   g_p0);
    cudaGetSymbolAddress((void**)&p_ctx2, g_ctx2);
    cudaGetSymbolAddress((void**)&p_t1,   g_t1);
    cudaGetSymbolAddress((void**)&p_pcw,  g_pcw);
    cudaGetSymbolAddress((void**)&p_p0v,  g_p0v);
    cudaGetSymbolAddress((void**)&p_vf1,  g_vf1);
    cudaGetSymbolAddress((void**)&p_vbf,  g_vbf);
    cudaGetSymbolAddress((void**)&p_CV,   g_CV);

    bool mk = gs.ok;
    cudaStream_t S0 = 0;
    cudaStream_t S1 = mk ? gs.s1 : (cudaStream_t)0;
    cudaStream_t S2 = mk ? gs.s2 : (cudaStream_t)0;
#define REC(ev, s)   do{ if (mk) cudaEventRecord(ev, s); }while(0)
#define WAITE(s, ev) do{ if (mk) cudaStreamWaitEvent(s, ev, 0); }while(0)

    REC(gs.ev0, S0);
    // S0: zeros + kv/gv
    k_prepzero<<<483,256,0,S0>>>(kw, sw, gw);
    REC(gs.evA, S0);

    // S1: p0 = emb@rel_w + rel_b
    WAITE(S1, gs.ev0);
    k_zp0<<<291,256,0,S1>>>();
    k_tcgemm<<<dim3(6,8,1),256,0,S1>>>(emb, rel_w, p_p0, rel_b, 97, 768, 96, 0);
    REC(gs.evP, S1);

    // S2: weight-only prep + p0-dependent side GEMMs
    WAITE(S2, gs.ev0);
    k_wprep<<<97,256,0,S2>>>(vw + (size_t)3*D_*D_, gw + (size_t)3*2*D_,
                             vb + (size_t)3*D_, gb + 3);
    WAITE(S2, gs.evA);
    WAITE(S2, gs.evP);
    k_tcgemm<<<dim3(6,8,1),256,0,S2>>>(p_p0, vw + (size_t)2*D_*D_, p_p0v, nullptr, 97, 768, 96, 0);
    REC(gs.evPV, S2);
    k_tcgemm<<<dim3(6,1,6),256,0,S2>>>(vw + (size_t)3*D_*D_, fc1w, p_vf1, nullptr, 768, 768, 768, 0);
    k_gemv_full<<<6,128,0,S2>>>(vb + (size_t)3*D_, fc1w, p_vbf);
    REC(gs.evVF, S2);
    k_tcgemm<<<dim3(6,8,1),256,0,S2>>>(p_p0, fc1w, p_pcw, nullptr, 97, 768, 96, 0);
    REC(gs.evQ, S2);

    // S1: l0 chain
    WAITE(S1, gs.evA);
    k_l0fused<<<1,1024,0,S1>>>();
    k_gemv<<<dim3(6,8),128,0,S1>>>(vw, vb);
    REC(gs.evB, S1);

    // S0: big x0 pass
    k_xprep<<<256,256,0,S0>>>(x_in, pos1, pos2);

    // S0 serial core
    WAITE(S0, gs.evB);
    k_gates<<<B_,512,0,S0>>>(0, mask, pos1, pos2, gw, gb);
    k_passB<<<256,256,0,S0>>>(x_in);
    k_tcgemm32<<<dim3(6,8),256,0,S0>>>(nullptr, vw + (size_t)1*D_*D_, p_ctx2, vb + 1*D_, 768, 96, 1);
    REC(gs.evC0, S0);

    // S2: CV = ctx2_0@vw2, pcw rows 97-128 = ctx2_0@fc1w (parallel with ra1_l1)
    WAITE(S2, gs.evC0);
    k_tcgemm32<<<dim3(6,8),256,0,S2>>>(p_ctx2, vw + (size_t)2*D_*D_, p_CV, nullptr, 768, 96, 0);
    REC(gs.evCV, S2);
    k_tcgemm32<<<dim3(6,8),256,0,S2>>>(p_ctx2, fc1w, p_pcw + (size_t)97*D_, nullptr, 768, 96, 0);
    REC(gs.evW, S2);

    WAITE(S0, gs.evPV);
    k_ra1_l1<<<B_,256,0,S0>>>(gw + (size_t)1*2*D_, gb + 1, vb + (size_t)2*D_);
    WAITE(S0, gs.evCV);
    k_gates<<<B_,512,0,S0>>>(1, mask, pos1, pos2, gw + (size_t)2*2*D_, gb + 2);
    REC(gs.evC, S0);

    // S1: t1 = [e1|e2]@fc1w[768:2304] + fc1b (parallel with tail)
    WAITE(S1, gs.evC);
    k_tcgemm32<<<dim3(6,8),256,0,S1>>>(nullptr, fc1w + (size_t)768*768, p_t1, fc1b, 1536, 192, 3);
    REC(gs.evT, S1);

    k_passB<<<256,256,0,S0>>>(x_in);
    WAITE(S0, gs.evVF);
    k_tcgemm32<<<dim3(6,8),256,0,S0>>>(nullptr, p_vf1, p_pcw + (size_t)129*D_, p_vbf, 768, 96, 2);

    WAITE(S0, gs.evT);
    WAITE(S0, gs.evQ);
    WAITE(S0, gs.evW);
    int wlog = (out_size >= GM) ? 1 : 0;
    int predoff = -1;
    if (out_size >= GM + B_) predoff = GM;
    else if (out_size == B_){ predoff = 0; wlog = 0; }
    k_tanh<<<B_,256,0,S0>>>(gw, gb, fc2w, fc2b, out, wlog, predoff);
#undef REC
#undef WAITE
}

// round 9
// speedup vs baseline: 1.3986x; 1.3986x over previous
#include <cuda_runtime.h>
#include <math.h>

#define B_ 32
#define L_ 512
#define D_ 768
#define C_ 97
#define GM (B_*C_)
#define BL (B_*L_)

// ---------------- scalar slots ----------------
// 0:ps1[32] 32:ps2 64:sagx0 96:P1g0 128:P2g0 160:sagx1a 192:sagx1b
// 224:P1g1 256:P2g1 288:sag1p
#define NSC 544

// ---------------- scratch ----------------
__device__ float g_bpart[12*B_*D_];  // grp0..3: a2@x0; grp4..7: pos1.x0; grp8..11: pos2.x0
__device__ float g_kv[4*D_];
__device__ float g_gv[4*D_];
__device__ float g_R[4*BL];
__device__ float g_g0[BL];
__device__ float g_a2[BL];
__device__ float g_sc[NSC];
__device__ float g_p0[C_*D_];
__device__ float g_pd[512];
__device__ float g_u0[D_];
__device__ float g_ctxA0[D_];
__device__ float g_p0v[C_*D_];       // p0@vw2 (atomic)
__device__ float g_cA1p[B_*D_];      // 2*(a1@p0v)+vb2 (direct)
__device__ float g_CV[B_*D_];        // ctx2_0@vw2 (atomic)
__device__ float g_ctx2[2*B_*D_];    // ctx2_0, ctx2_1 (atomic)
__device__ float g_t1[B_*D_];
__device__ float g_pcw[161*D_];      // rows0-96 p0W, 97-128 ctx2_0W, 129-160 ctx2_1W

__device__ __forceinline__ float warpsum(float v){
#pragma unroll
    for (int o = 16; o > 0; o >>= 1) v += __shfl_xor_sync(0xffffffffu, v, o);
    return v;
}
__device__ __forceinline__ float warpmax(float v){
#pragma unroll
    for (int o = 16; o > 0; o >>= 1) v = fmaxf(v, __shfl_xor_sync(0xffffffffu, v, o));
    return v;
}
__device__ __forceinline__ float sigm(float z){ return 1.f/(1.f + expf(-z)); }
__device__ __forceinline__ unsigned f2tf(float f){
    unsigned u; asm("cvt.rna.tf32.f32 %0, %1;" : "=r"(u) : "f"(f)); return u;
}
__device__ __forceinline__ void mma_tf32(float c[4], unsigned a0, unsigned a1,
                                         unsigned a2, unsigned a3,
                                         unsigned b0, unsigned b1){
    asm volatile("mma.sync.aligned.m16n8k8.row.col.f32.tf32.tf32.f32 "
        "{%0,%1,%2,%3}, {%4,%5,%6,%7}, {%8,%9}, {%0,%1,%2,%3};\n"
        : "+f"(c[0]), "+f"(c[1]), "+f"(c[2]), "+f"(c[3])
        : "r"(a0), "r"(a1), "r"(a2), "r"(a3), "r"(b0), "r"(b1));
}
__device__ __forceinline__ float blockdot768(const float* __restrict__ a,
                                             const float* __restrict__ v,
                                             float* sh, int nthr){
    int tid = threadIdx.x, lane = tid & 31, w = tid >> 5;
    float p = 0.f;
    for (int e = tid; e < D_; e += nthr) p += a[e]*v[e];
    p = warpsum(p);
    __syncthreads();
    if (!lane) sh[w] = p;
    __syncthreads();
    float r = 0.f;
    int nw = nthr >> 5;
    for (int i = 0; i < nw; i++) r += sh[i];
    return r;
}

// ---------------- zero p0 ----------------
__global__ void k_zp0(){
    int i = blockIdx.x*256 + threadIdx.x;
    if (i < C_*D_) g_p0[i] = 0.f;
}

// ---------------- zeros + kv/gv prep ----------------
__global__ void __launch_bounds__(256) k_prepzero(const float* __restrict__ kw,
                                                  const float* __restrict__ sw,
                                                  const float* __restrict__ gw){
    int gtid = blockIdx.x*blockDim.x + threadIdx.x;
    if (gtid < NSC) g_sc[gtid] = 0.f;
    if (gtid < D_) g_ctxA0[gtid] = 0.f;
    if (gtid < B_*D_){ g_CV[gtid] = 0.f; g_t1[gtid] = 0.f; }
    if (gtid < 2*B_*D_) g_ctx2[gtid] = 0.f;
    if (gtid < 161*D_) g_pcw[gtid] = 0.f;
    if (gtid < C_*D_) g_p0v[gtid] = 0.f;
    if (gtid < 4*D_){
        int ra = gtid/D_, dd = gtid%D_;
        const float* g = gw + (size_t)ra*2*D_;
        g_gv[gtid] = g[dd] + g[D_+dd];
    }
    int wid = gtid >> 5, lane = gtid & 31;
    if (wid < 4*D_){
        int ra = wid/D_, d = wid%D_;
        const float* krow = kw + ((size_t)ra*D_ + d)*D_;
        const float* s2   = sw + (size_t)ra*2*D_ + D_;
        float acc = 0.f;
        for (int e = lane; e < D_; e += 32) acc += krow[e]*s2[e];
        acc = warpsum(acc);
        if (!lane) g_kv[wid] = acc;
    }
}

// ---------------- one pass over x0 (4 chunks of 128 rows, proven in R7) -----
__global__ void __launch_bounds__(256) k_xprep(const float* __restrict__ x0,
                                               const float* __restrict__ pos1,
                                               const float* __restrict__ pos2){
    int blk = blockIdx.x; int b = blk >> 2, ch = blk & 3;
    int tid = threadIdx.x;
    int wid = tid >> 5, lane = tid & 31;
    int base = b*L_ + ch*128;
    for (int r = wid; r < 128; r += 8){
        const float* xr = x0 + (size_t)(base+r)*D_;
        float a0=0.f, a1=0.f, a2=0.f, a3=0.f;
#pragma unroll
        for (int j = 0; j < 24; j++){
            int e = lane + j*32; float xv = xr[e];
            a0 += xv*g_gv[e];
            a1 += xv*g_kv[D_+e];
            a2 += xv*g_gv[2*D_+e];
            a3 += xv*g_kv[3*D_+e];
        }
        a0=warpsum(a0); a1=warpsum(a1); a2=warpsum(a2); a3=warpsum(a3);
        if (!lane){
            int row = base + r;
            g_R[row] = a0; g_R[BL+row] = a1; g_R[2*BL+row] = a2; g_R[3*BL+row] = a3;
        }
    }
    __shared__ float s1[128], s2[128];
    if (tid < 128){ s1[tid] = pos1[base+tid]; s2[tid] = pos2[base+tid]; }
    __syncthreads();
#pragma unroll
    for (int c0 = 0; c0 < 3; c0++){
        int col = tid + c0*256;
        const float* xb = x0 + (size_t)base*D_ + col;
        float e1 = 0.f, e2 = 0.f;
        for (int l = 0; l < 128; l++){
            float xv = xb[(size_t)l*D_];
            e1 += s1[l]*xv; e2 += s2[l]*xv;
        }
        g_bpart[((4+ch)*B_ + b)*D_ + col] = e1;
        g_bpart[((8+ch)*B_ + b)*D_ + col] = e2;
    }
    if (tid == 0){
        float t1 = 0.f, t2 = 0.f;
        for (int l = 0; l < 128; l++){ t1 += s1[l]; t2 += s2[l]; }
        atomicAdd(&g_sc[b], t1); atomicAdd(&g_sc[32+b], t2);
    }
}

// ---------------- fused: pdots + layer0 softmax + u0 ----------------
__global__ void __launch_bounds__(1024) k_l0fused(){
    __shared__ float a[C_];
    int tid = threadIdx.x;
    int wid = tid >> 5, lane = tid & 31;
    for (int c = wid; c < C_; c += 32){
        const float* pr = g_p0 + (size_t)c*D_;
        float a0=0.f,a1=0.f,a2=0.f,a3=0.f;
#pragma unroll
        for (int j=0;j<24;j++){
            int e = lane + j*32; float pv = pr[e];
            a0 += pv*g_kv[e];
            a1 += pv*g_kv[2*D_+e];
            a2 += pv*g_gv[D_+e];
            a3 += pv*g_gv[3*D_+e];
        }
        a0=warpsum(a0);a1=warpsum(a1);a2=warpsum(a2);a3=warpsum(a3);
        if (!lane){ g_pd[c]=a0; g_pd[128+c]=a1; g_pd[256+c]=a2; g_pd[384+c]=a3;
                    a[c] = a0; }
    }
    __syncthreads();
    if (tid == 0){
        float m = -1e30f;
        for (int c=0;c<C_;c++) m = fmaxf(m, a[c]);
        float s = 0.f;
        for (int c=0;c<C_;c++){ a[c] = expf(a[c]-m); s += a[c]; }
        float inv = 1.f/s;
        for (int c=0;c<C_;c++) a[c] *= inv;
    }
    __syncthreads();
    if (tid < D_){
        float acc = 0.f;
        for (int c=0;c<C_;c++) acc += a[c]*g_p0[(size_t)c*D_+tid];
        g_u0[tid] = acc;
    }
}

// ---------------- GEMV (atomic, split-8): ctxA0 = u0@W + bias ----------------
__global__ void __launch_bounds__(128) k_gemv(const float* __restrict__ W,
                                              const float* __restrict__ bias){
    int n = blockIdx.x*128 + threadIdx.x;
    int kc = blockIdx.y;
    float acc = (kc==0) ? bias[n] : 0.f;
    const float* Wp = W + (size_t)kc*96*D_ + n;
    const float* u = g_u0 + kc*96;
#pragma unroll 4
    for (int k=0;k<96;k++) acc += u[k]*Wp[(size_t)k*D_];
    atomicAdd(&g_ctxA0[n], acc);
}

// ---------------- gates + masked softmax + scalar reductions ----------------
__global__ void __launch_bounds__(512) k_gates(int li, const int* __restrict__ mask,
                        const float* __restrict__ pos1, const float* __restrict__ pos2,
                        const float* __restrict__ gwp, const float* __restrict__ gbp){
    int b = blockIdx.x, tid = threadIdx.x;
    __shared__ float sh[16];
    __shared__ float sc[4];
    if (li == 0){
        float d0 = blockdot768(g_ctxA0, gwp, sh, 512);
        float d1 = blockdot768(g_ctxA0, g_kv + D_, sh, 512);
        if (tid == 0){ sc[0] = d0 + gbp[0]; sc[1] = d1; }
    } else {
        const float* cp = g_cA1p + (size_t)b*D_;
        const float* cv = g_CV + (size_t)b*D_;
        float sag = g_sc[288+b];
        float d0a = blockdot768(cp, gwp, sh, 512);
        float d0b = blockdot768(cv, gwp, sh, 512);
        float d1 = blockdot768(g_ctxA0, g_gv + 2*D_, sh, 512);
        float d2 = blockdot768(g_ctxA0, g_kv + 3*D_, sh, 512);
        float d3a = blockdot768(cp, g_kv + 3*D_, sh, 512);
        float d3b = blockdot768(cv, g_kv + 3*D_, sh, 512);
        if (tid == 0){
            sc[0] = d0a + sag*d0b + gbp[0];
            sc[1] = d1; sc[2] = d2;
            sc[3] = d3a + sag*d3b;
        }
    }
    __syncthreads();
    int row = b*L_ + tid;
    float g, sk, g0v = 0.f;
    if (li == 0){
        g = sigm(g_R[row] + sc[0]);
        sk = 2.f*g_R[BL+row] + g*sc[1];
        g_g0[row] = g;
    } else {
        g0v = g_g0[row];
        g = sigm(2.f*g_R[2*BL+row] + g0v*sc[1] + sc[0]);
        sk = 4.f*g_R[3*BL+row] + 2.f*g0v*sc[2] + g*sc[3];
    }
    if (!mask[row]) sk = -1e30f;
    __shared__ float sm[16];
    __shared__ float bc;
    float m = warpmax(sk);
    if ((tid & 31) == 0) sm[tid>>5] = m;
    __syncthreads();
    if (tid == 0){
        float mm = sm[0];
        for (int i = 1; i < 16; i++) mm = fmaxf(mm, sm[i]);
        bc = mm;
    }
    __syncthreads();
    float e = expf(sk - bc);
    float ssum = warpsum(e);
    __syncthreads();
    if ((tid & 31) == 0) sm[tid>>5] = ssum;
    __syncthreads();
    if (tid == 0){
        float ss = 0.f;
        for (int i = 0; i < 16; i++) ss += sm[i];
        bc = ss;
    }
    __syncthreads();
    float a = e / bc;
    g_a2[row] = a;
    __shared__ float red[16][4];
    float r0, r1, r2, r3;
    if (li == 0){ r0 = a*g; r1 = pos1[row]*g; r2 = pos2[row]*g; r3 = 0.f; }
    else        { r0 = a*g0v; r1 = a*g; r2 = pos1[row]*g; r3 = pos2[row]*g; }
    r0=warpsum(r0); r1=warpsum(r1); r2=warpsum(r2); r3=warpsum(r3);
    if ((tid & 31) == 0){
        int w = tid>>5;
        red[w][0]=r0; red[w][1]=r1; red[w][2]=r2; red[w][3]=r3;
    }
    __syncthreads();
    if (tid == 0){
        float t0=0,t1=0,t2=0,t3=0;
        for (int i = 0; i < 16; i++){ t0+=red[i][0]; t1+=red[i][1]; t2+=red[i][2]; t3+=red[i][3]; }
        if (li == 0){ g_sc[64+b]=t0; g_sc[96+b]=t1; g_sc[128+b]=t2; }
        else        { g_sc[160+b]=t0; g_sc[192+b]=t1; g_sc[224+b]=t2; g_sc[256+b]=t3; }
    }
}

// ---------------- passB: a2 @ x0 partials (4 chunks) ----------------
__global__ void __launch_bounds__(256) k_passB(const float* __restrict__ x0){
    int blk = blockIdx.x; int b = blk >> 2, ch = blk & 3;
    int tid = threadIdx.x;
    __shared__ float sa[128];
    if (tid < 128) sa[tid] = g_a2[b*L_ + ch*128 + tid];
    __syncthreads();
#pragma unroll
    for (int c0 = 0; c0 < 3; c0++){
        int col = tid + c0*256;
        const float* xb = x0 + ((size_t)b*L_ + ch*128)*D_ + col;
        float au = 0.f;
        for (int l = 0; l < 128; l++) au += sa[l]*xb[(size_t)l*D_];
        g_bpart[(ch*B_ + b)*D_ + col] = au;
    }
}

// ---------------- layer1 RA1: softmax over C + cA1p = 2*(a1@P0V)+vb2 --------
__global__ void __launch_bounds__(256) k_ra1_l1(const float* __restrict__ gwp,
                                                const float* __restrict__ gbp,
                                                const float* __restrict__ vb2){
    int b = blockIdx.x, tid = threadIdx.x;
    __shared__ float sh[8];
    __shared__ float sc2[2];
    __shared__ float a1[C_], g0p[C_];
    const float* c20 = g_ctx2 + (size_t)b*D_;
    float d0 = blockdot768(c20, gwp, sh, 256);
    float d1 = blockdot768(c20, g_kv + 2*D_, sh, 256);
    if (tid == 0){ sc2[0] = d0 + gbp[0]; sc2[1] = d1; }
    __syncthreads();
    if (tid < C_){
        float gp = sigm(g_pd[256+tid] + sc2[0]);
        g0p[tid] = gp;
        a1[tid] = 2.f*g_pd[128+tid] + gp*sc2[1];
    }
    __syncthreads();
    if (tid == 0){
        float m = -1e30f;
        for (int c=0;c<C_;c++) m = fmaxf(m, a1[c]);
        float s = 0.f;
        for (int c=0;c<C_;c++){ a1[c] = expf(a1[c]-m); s += a1[c]; }
        float inv = 1.f/s, sg = 0.f;
        for (int c=0;c<C_;c++){ a1[c] *= inv; sg += a1[c]*g0p[c]; }
        g_sc[288+b] = sg;
    }
    __syncthreads();
    for (int n = tid; n < D_; n += 256){
        float s = 0.f;
        for (int c=0;c<C_;c++) s += a1[c]*g_p0v[(size_t)c*D_+n];
        g_cA1p[b*D_+n] = 2.f*s + vb2[n];
    }
}

// ---------------- A-assembly ----------------
__device__ __forceinline__ float4 f4sum4(int grp, int m, int kg){
    float4 a = *(const float4*)(g_bpart + ((size_t)(grp+0)*B_+m)*D_ + kg);
    float4 b = *(const float4*)(g_bpart + ((size_t)(grp+1)*B_+m)*D_ + kg);
    float4 c = *(const float4*)(g_bpart + ((size_t)(grp+2)*B_+m)*D_ + kg);
    float4 d = *(const float4*)(g_bpart + ((size_t)(grp+3)*B_+m)*D_ + kg);
    return make_float4(a.x+b.x+c.x+d.x, a.y+b.y+c.y+d.y, a.z+b.z+c.z+d.z, a.w+b.w+c.w+d.w);
}
__device__ __forceinline__ float4 loadA4(const float* __restrict__ A, int amode,
                                         int m, int M, int kg, int K){
    if (m >= M) return make_float4(0.f,0.f,0.f,0.f);
    if (amode == 0) return *(const float4*)(A + (size_t)m*K + kg);
    if (amode == 1){
        float4 s = f4sum4(0, m, kg);
        float4 c = *(const float4*)(g_ctxA0 + kg);
        float sg = g_sc[64+m];
        return make_float4(2.f*s.x+sg*c.x, 2.f*s.y+sg*c.y, 2.f*s.z+sg*c.z, 2.f*s.w+sg*c.w);
    }
    if (amode == 2){
        float4 s = f4sum4(0, m, kg);
        float4 c0 = *(const float4*)(g_ctxA0 + kg);
        float4 p = *(const float4*)(g_cA1p + (size_t)m*D_ + kg);
        float4 cv = *(const float4*)(g_CV + (size_t)m*D_ + kg);
        float sag = g_sc[288+m];
        float sa = 2.f*g_sc[160+m], sb = g_sc[192+m];
        return make_float4(4.f*s.x+sa*c0.x+sb*(p.x+sag*cv.x),
                           4.f*s.y+sa*c0.y+sb*(p.y+sag*cv.y),
                           4.f*s.z+sa*c0.z+sb*(p.z+sag*cv.z),
                           4.f*s.w+sa*c0.w+sb*(p.w+sag*cv.w));
    }
    // amode 3: e12
    int grp = (kg < D_) ? 4 : 8;
    int k2 = (kg < D_) ? kg : kg - D_;
    float4 s = f4sum4(grp, m, k2);
    float4 c0 = *(const float4*)(g_ctxA0 + k2);
    float4 p = *(const float4*)(g_cA1p + (size_t)m*D_ + k2);
    float4 cv = *(const float4*)(g_CV + (size_t)m*D_ + k2);
    float sag = g_sc[288+m];
    float pg0 = 2.f*((kg < D_) ? g_sc[96+m] : g_sc[128+m]);
    float pg1 = (kg < D_) ? g_sc[224+m] : g_sc[256+m];
    float inv = 1.f/((kg < D_) ? g_sc[m] : g_sc[32+m]);
    return make_float4((4.f*s.x+pg0*c0.x+pg1*(p.x+sag*cv.x))*inv,
                       (4.f*s.y+pg0*c0.y+pg1*(p.y+sag*cv.y))*inv,
                       (4.f*s.z+pg0*c0.z+pg1*(p.z+sag*cv.z))*inv,
                       (4.f*s.w+pg0*c0.w+pg1*(p.w+sag*cv.w))*inv);
}

// ---------------- generic 128-row TF32 split-K GEMM ----------------
__global__ void __launch_bounds__(256) k_tcgemm(const float* __restrict__ A,
        const float* __restrict__ W, float* __restrict__ out,
        const float* __restrict__ bias, int M, int K, int KCH, int amode){
    __shared__ unsigned As[2][128][20];
    __shared__ unsigned Bs[2][16][132];
    int tid = threadIdx.x;
    int lane = tid & 31, g = lane >> 2, tg = lane & 3;
    int wid = tid >> 5, wm = wid >> 2, wn = wid & 3;
    int n0 = blockIdx.x * 128;
    int kb = blockIdx.y;
    int m0 = blockIdx.z * 128;
    int kbase = kb * KCH;
    int NS = KCH / 16;

    float cacc[4][4][4];
#pragma unroll
    for (int i = 0; i < 4; i++)
#pragma unroll
        for (int j = 0; j < 4; j++)
#pragma unroll
            for (int q = 0; q < 4; q++) cacc[i][j][q] = 0.f;

    int a_r = tid >> 2, a_c = (tid & 3) * 4;
    int b_r = tid >> 5, b_c = (tid & 31) * 4;

    float4 pa[2], pb[2];
#pragma unroll
    for (int r = 0; r < 2; r++){
        pa[r] = loadA4(A, amode, m0 + a_r + r*64, M, kbase + a_c, K);
        pb[r] = *(const float4*)(W + (size_t)(kbase + b_r + r*8)*D_ + n0 + b_c);
    }
#pragma unroll
    for (int r = 0; r < 2; r++){
        uint4 ua = { f2tf(pa[r].x), f2tf(pa[r].y), f2tf(pa[r].z), f2tf(pa[r].w) };
        *(uint4*)&As[0][a_r + r*64][a_c] = ua;
        uint4 ub = { f2tf(pb[r].x), f2tf(pb[r].y), f2tf(pb[r].z), f2tf(pb[r].w) };
        *(uint4*)&Bs[0][b_r + r*8][b_c] = ub;
    }
    __syncthreads();

    for (int s = 0; s < NS; s++){
        int cur = s & 1;
        if (s < NS-1){
            int kg = kbase + (s+1)*16;
#pragma unroll
            for (int r = 0; r < 2; r++){
                pa[r] = loadA4(A, amode, m0 + a_r + r*64, M, kg + a_c, K);
                pb[r] = *(const float4*)(W + (size_t)(kg + b_r + r*8)*D_ + n0 + b_c);
            }
        }
#pragma unroll
        for (int ks = 0; ks < 2; ks++){
            int k8 = ks*8;
            unsigned af[4][4], bf[4][2];
#pragma unroll
            for (int i = 0; i < 4; i++){
                int r = wm*64 + i*16 + g;
                af[i][0] = As[cur][r][k8+tg];
                af[i][1] = As[cur][r+8][k8+tg];
                af[i][2] = As[cur][r][k8+tg+4];
                af[i][3] = As[cur][r+8][k8+tg+4];
            }
#pragma unroll
            for (int j = 0; j < 4; j++){
                int c0 = wn*32 + j*8 + g;
                bf[j][0] = Bs[cur][k8+tg][c0];
                bf[j][1] = Bs[cur][k8+tg+4][c0];
            }
#pragma unroll
            for (int i = 0; i < 4; i++)
#pragma unroll
                for (int j = 0; j < 4; j++)
                    mma_tf32(cacc[i][j], af[i][0], af[i][1], af[i][2], af[i][3],
                             bf[j][0], bf[j][1]);
        }
        if (s < NS-1){
            int nxt = cur ^ 1;
#pragma unroll
            for (int r = 0; r < 2; r++){
                uint4 ua = { f2tf(pa[r].x), f2tf(pa[r].y), f2tf(pa[r].z), f2tf(pa[r].w) };
                *(uint4*)&As[nxt][a_r + r*64][a_c] = ua;
                uint4 ub = { f2tf(pb[r].x), f2tf(pb[r].y), f2tf(pb[r].z), f2tf(pb[r].w) };
                *(uint4*)&Bs[nxt][b_r + r*8][b_c] = ub;
            }
        }
        __syncthreads();
    }

#pragma unroll
    for (int i = 0; i < 4; i++){
#pragma unroll
        for (int half = 0; half < 2; half++){
            int m = m0 + wm*64 + i*16 + g + half*8;
            if (m < M){
#pragma unroll
                for (int j = 0; j < 4; j++){
                    int n = n0 + wn*32 + j*8 + 2*tg;
                    float v0 = cacc[i][j][half*2+0];
                    float v1 = cacc[i][j][half*2+1];
                    if (kb == 0 && bias){ v0 += bias[n]; v1 += bias[n+1]; }
                    atomicAdd(out + (size_t)m*D_ + n,     v0);
                    atomicAdd(out + (size_t)m*D_ + n + 1, v1);
                }
            }
        }
    }
}

// ---------------- dedicated M=32 TF32 split-K GEMM ----------------
__global__ void __launch_bounds__(256) k_tcgemm32(const float* __restrict__ A,
        const float* __restrict__ W, float* __restrict__ out,
        const float* __restrict__ bias, int K, int KCH, int amode){
    __shared__ unsigned As[2][32][20];
    __shared__ unsigned Bs[2][16][132];
    const int M = 32;
    int tid = threadIdx.x;
    int lane = tid & 31, g = lane >> 2, tg = lane & 3;
    int wid = tid >> 5, wm = wid >> 2, wn = wid & 3;
    int n0 = blockIdx.x * 128;
    int kb = blockIdx.y;
    int kbase = kb * KCH;
    int NS = KCH / 16;

    float cacc[4][4];
#pragma unroll
    for (int j = 0; j < 4; j++)
#pragma unroll
        for (int q = 0; q < 4; q++) cacc[j][q] = 0.f;

    int a_r = tid >> 2, a_c = (tid & 3) * 4;
    int b_r = tid >> 5, b_c = (tid & 31) * 4;

    float4 pa = make_float4(0.f,0.f,0.f,0.f), pb[2];
    if (tid < 128) pa = loadA4(A, amode, a_r, M, kbase + a_c, K);
#pragma unroll
    for (int r = 0; r < 2; r++)
        pb[r] = *(const float4*)(W + (size_t)(kbase + b_r + r*8)*D_ + n0 + b_c);
    if (tid < 128){
        uint4 ua = { f2tf(pa.x), f2tf(pa.y), f2tf(pa.z), f2tf(pa.w) };
        *(uint4*)&As[0][a_r][a_c] = ua;
    }
#pragma unroll
    for (int r = 0; r < 2; r++){
        uint4 ub = { f2tf(pb[r].x), f2tf(pb[r].y), f2tf(pb[r].z), f2tf(pb[r].w) };
        *(uint4*)&Bs[0][b_r + r*8][b_c] = ub;
    }
    __syncthreads();

    for (int s = 0; s < NS; s++){
        int cur = s & 1;
        if (s < NS-1){
            int kg = kbase + (s+1)*16;
            if (tid < 128) pa = loadA4(A, amode, a_r, M, kg + a_c, K);
#pragma unroll
            for (int r = 0; r < 2; r++)
                pb[r] = *(const float4*)(W + (size_t)(kg + b_r + r*8)*D_ + n0 + b_c);
        }
#pragma unroll
        for (int ks = 0; ks < 2; ks++){
            int k8 = ks*8;
            unsigned af[4], bf[4][2];
            int r = wm*16 + g;
            af[0] = As[cur][r][k8+tg];
            af[1] = As[cur][r+8][k8+tg];
            af[2] = As[cur][r][k8+tg+4];
            af[3] = As[cur][r+8][k8+tg+4];
#pragma unroll
            for (int j = 0; j < 4; j++){
                int c0 = wn*32 + j*8 + g;
                bf[j][0] = Bs[cur][k8+tg][c0];
                bf[j][1] = Bs[cur][k8+tg+4][c0];
            }
#pragma unroll
            for (int j = 0; j < 4; j++)
                mma_tf32(cacc[j], af[0], af[1], af[2], af[3], bf[j][0], bf[j][1]);
        }
        if (s < NS-1){
            int nxt = cur ^ 1;
            if (tid < 128){
                uint4 ua = { f2tf(pa.x), f2tf(pa.y), f2tf(pa.z), f2tf(pa.w) };
                *(uint4*)&As[nxt][a_r][a_c] = ua;
            }
#pragma unroll
            for (int r = 0; r < 2; r++){
                uint4 ub = { f2tf(pb[r].x), f2tf(pb[r].y), f2tf(pb[r].z), f2tf(pb[r].w) };
                *(uint4*)&Bs[nxt][b_r + r*8][b_c] = ub;
            }
        }
        __syncthreads();
    }

#pragma unroll
    for (int half = 0; half < 2; half++){
        int m = wm*16 + g + half*8;
#pragma unroll
        for (int j = 0; j < 4; j++){
            int n = n0 + wn*32 + j*8 + 2*tg;
            float v0 = cacc[j][half*2+0];
            float v1 = cacc[j][half*2+1];
            if (kb == 0 && bias){ v0 += bias[n]; v1 += bias[n+1]; }
            atomicAdd(out + (size_t)m*D_ + n,     v0);
            atomicAdd(out + (size_t)m*D_ + n + 1, v1);
        }
    }
}

// ---------------- final: tanh recombination + logits + argmax ----------------
__global__ void __launch_bounds__(256) k_tanh(const float* __restrict__ gw,
        const float* __restrict__ gb, const float* __restrict__ fc2w,
        const float* __restrict__ fc2b, float* __restrict__ out,
        int wlog, int predoff){
    int b = blockIdx.x, tid = threadIdx.x, lane = tid & 31, wid = tid >> 5;
    __shared__ float sh[8];
    __shared__ float cw0[D_], cw1[D_], t1s[D_], w2[D_];
    __shared__ float sc3[3];
    __shared__ float lg[C_];
    const float* c20 = g_ctx2 + (size_t)b*D_;
    const float* c21 = g_ctx2 + (size_t)(B_+b)*D_;
    for (int e = tid; e < D_; e += 256){
        cw0[e] = g_pcw[(size_t)(97+b)*D_+e];
        cw1[e] = g_pcw[(size_t)(129+b)*D_+e];
        t1s[e] = g_t1[b*D_+e];
        w2[e]  = fc2w[e];
    }
    float d0 = blockdot768(c20, gw + 1*2*D_, sh, 256);
    float d1 = blockdot768(c20, g_gv + 3*D_, sh, 256);
    float d2 = blockdot768(c21, gw + 3*2*D_, sh, 256);
    if (tid == 0){ sc3[0] = d0 + gb[1]; sc3[1] = d1; sc3[2] = d2 + gb[3]; }
    __syncthreads();
    for (int c = wid; c < C_; c += 8){
        float gp0 = sigm(g_pd[256+c] + sc3[0]);
        float gp1 = sigm(2.f*g_pd[384+c] + gp0*sc3[1] + sc3[2]);
        const float* pw = g_pcw + (size_t)c*D_;
        float acc = 0.f;
#pragma unroll
        for (int j = 0; j < 24; j++){
            int n = lane + j*32;
            float z = 4.f*pw[n] + 2.f*gp0*cw0[n] + gp1*cw1[n] + t1s[n];
            acc += tanhf(z)*w2[n];
        }
        acc = warpsum(acc);
        if (!lane){
            float l = sigm(acc + fc2b[0]);
            lg[c] = l;
            if (wlog) out[b*C_+c] = l;
        }
    }
    __syncthreads();
    if (tid == 0 && predoff >= 0){
        float best = lg[0]; int bi = 0;
        for (int c = 1; c < C_; c++)
            if (lg[c] > best){ best = lg[c]; bi = c; }
        out[predoff + b] = (float)bi;
    }
}

// ---------------- streams, created+warmed at load time ----------------
namespace {
struct GStreams {
    cudaStream_t s1 = 0, s2 = 0;
    cudaEvent_t ev0, evA, evP, evPV, evB, evC0, evCV, evQ, evW, evC, evT;
    bool ok = false;
    GStreams(){
        bool o = true;
        o = o && cudaStreamCreateWithFlags(&s1, cudaStreamNonBlocking) == cudaSuccess;
        o = o && cudaStreamCreateWithFlags(&s2, cudaStreamNonBlocking) == cudaSuccess;
        cudaEvent_t* evs[11] = {&ev0,&evA,&evP,&evPV,&evB,&evC0,&evCV,&evQ,&evW,&evC,&evT};
        for (int i = 0; i < 11 && o; i++)
            o = o && cudaEventCreateWithFlags(evs[i], cudaEventDisableTiming) == cudaSuccess;
        if (o){
            k_zp0<<<291,256,0,s1>>>();
            k_zp0<<<291,256,0,s2>>>();
            o = o && cudaStreamSynchronize(s1) == cudaSuccess;
            o = o && cudaStreamSynchronize(s2) == cudaSuccess;
        }
        ok = o;
    }
};
GStreams gs;
}

// ---------------- host orchestration ----------------
extern "C" void kernel_launch(void* const* d_in, const int* in_sizes, int n_in,
                              void* d_out, int out_size){
    (void)in_sizes; (void)n_in;
    const float* x_in  = (const float*)d_in[0];
    const float* pos1  = (const float*)d_in[1];
    const float* pos2  = (const float*)d_in[2];
    const int*   mask  = (const int*)  d_in[3];
    const float* emb   = (const float*)d_in[4];
    const float* rel_w = (const float*)d_in[5];
    const float* rel_b = (const float*)d_in[6];
    const float* kw    = (const float*)d_in[9];
    const float* vw    = (const float*)d_in[11];
    const float* vb    = (const float*)d_in[12];
    const float* sw    = (const float*)d_in[13];
    const float* gw    = (const float*)d_in[15];
    const float* gb    = (const float*)d_in[16];
    const float* fc1w  = (const float*)d_in[17];
    const float* fc1b  = (const float*)d_in[18];
    const float* fc2w  = (const float*)d_in[19];
    const float* fc2b  = (const float*)d_in[20];
    float* out = (float*)d_out;

    float *p_p0, *p_ctx2, *p_t1, *p_pcw, *p_p0v, *p_CV;
    cudaGetSymbolAddress((void**)&p_p0,   g_p0);
    cudaGetSymbolAddress((void**)&p_ctx2, g_ctx2);
    cudaGetSymbolAddress((void**)&p_t1,   g_t1);
    cudaGetSymbolAddress((void**)&p_pcw,  g_pcw);
    cudaGetSymbolAddress((void**)&p_p0v,  g_p0v);
    cudaGetSymbolAddress((void**)&p_CV,   g_CV);

    bool mk = gs.ok;
    cudaStream_t S0 = 0;
    cudaStream_t S1 = mk ? gs.s1 : (cudaStream_t)0;
    cudaStream_t S2 = mk ? gs.s2 : (cudaStream_t)0;
#define REC(ev, s)   do{ if (mk) cudaEventRecord(ev, s); }while(0)
#define WAITE(s, ev) do{ if (mk) cudaStreamWaitEvent(s, ev, 0); }while(0)

    REC(gs.ev0, S0);
    // S0: zeros + kv/gv
    k_prepzero<<<483,256,0,S0>>>(kw, sw, gw);
    REC(gs.evA, S0);

    // S1: p0 = emb@rel_w + rel_b
    WAITE(S1, gs.ev0);
    k_zp0<<<291,256,0,S1>>>();
    k_tcgemm<<<dim3(6,8,1),256,0,S1>>>(emb, rel_w, p_p0, rel_b, 97, 768, 96, 0);
    REC(gs.evP, S1);

    // S2: p0-dependent side GEMMs (light; done long before needed)
    WAITE(S2, gs.evA);
    WAITE(S2, gs.evP);
    k_tcgemm<<<dim3(6,8,1),256,0,S2>>>(p_p0, vw + (size_t)2*D_*D_, p_p0v, nullptr, 97, 768, 96, 0);
    REC(gs.evPV, S2);
    k_tcgemm<<<dim3(6,8,1),256,0,S2>>>(p_p0, fc1w, p_pcw, nullptr, 97, 768, 96, 0);
    REC(gs.evQ, S2);

    // S1: l0 chain
    WAITE(S1, gs.evA);
    k_l0fused<<<1,1024,0,S1>>>();
    k_gemv<<<dim3(6,8),128,0,S1>>>(vw, vb);
    REC(gs.evB, S1);

    // S0: big x0 pass (overlaps with S1/S2)
    k_xprep<<<128,256,0,S0>>>(x_in, pos1, pos2);

    // S0 serial core
    WAITE(S0, gs.evB);
    k_gates<<<B_,512,0,S0>>>(0, mask, pos1, pos2, gw, gb);
    k_passB<<<128,256,0,S0>>>(x_in);
    k_tcgemm32<<<dim3(6,8),256,0,S0>>>(nullptr, vw + (size_t)1*D_*D_, p_ctx2, vb + 1*D_, 768, 96, 1);
    REC(gs.evC0, S0);

    // S2: CV = ctx2_0@vw2 (needed by gates1), then pcw rows 97-128
    WAITE(S2, gs.evC0);
    k_tcgemm32<<<dim3(6,8),256,0,S2>>>(p_ctx2, vw + (size_t)2*D_*D_, p_CV, nullptr, 768, 96, 0);
    REC(gs.evCV, S2);
    k_tcgemm32<<<dim3(6,8),256,0,S2>>>(p_ctx2, fc1w, p_pcw + (size_t)97*D_, nullptr, 768, 96, 0);
    REC(gs.evW, S2);

    // S0: ra1_l1 (parallel with CV on S2), then gates1
    WAITE(S0, gs.evPV);
    k_ra1_l1<<<B_,256,0,S0>>>(gw + (size_t)1*2*D_, gb + 1, vb + (size_t)2*D_);
    WAITE(S0, gs.evCV);
    k_gates<<<B_,512,0,S0>>>(1, mask, pos1, pos2, gw + (size_t)2*2*D_, gb + 2);
    REC(gs.evC, S0);

    // S1: t1 = [e1|e2]@fc1w[768:2304] + fc1b (parallel with S0 tail)
    WAITE(S1, gs.evC);
    k_tcgemm32<<<dim3(6,8),256,0,S1>>>(nullptr, fc1w + (size_t)768*768, p_t1, fc1b, 1536, 192, 3);
    REC(gs.evT, S1);

    k_passB<<<128,256,0,S0>>>(x_in);
    k_tcgemm32<<<dim3(6,8),256,0,S0>>>(nullptr, vw + (size_t)3*D_*D_, p_ctx2 + (size_t)B_*D_, vb + 3*D_, 768, 96, 2);
    k_tcgemm32<<<dim3(6,8),256,0,S0>>>(p_ctx2 + (size_t)B_*D_, fc1w, p_pcw + (size_t)129*D_, nullptr, 768, 96, 0);

    WAITE(S0, gs.evT);
    WAITE(S0, gs.evQ);
    WAITE(S0, gs.evW);
    int wlog = (out_size >= GM) ? 1 : 0;
    int predoff = -1;
    if (out_size >= GM + B_) predoff = GM;
    else if (out_size == B_){ predoff = 0; wlog = 0; }
    k_tanh<<<B_,256,0,S0>>>(gw, gb, fc2w, fc2b, out, wlog, predoff);
#undef REC
#undef WAITE
}